// round 4
// baseline (speedup 1.0000x reference)
#include <cuda_runtime.h>
#include <math.h>
#include <stdint.h>

#define NTOK 4096
#define NB   16
#define NC   256
#define NH   128
#define TOTAL (NTOK*NB)
#define STR  36   // smem row stride (floats): bank = (4*row + col) % 32, conflict-free frags

// ---------------- device scratch ----------------
__device__ float         g_sig[TOTAL];
__device__ unsigned char g_cat[TOTAL];
__device__ int           g_splitWork[TOTAL];  // rank r -> n | n<<16 (split tokens ascending)
__device__ int           g_pairWork[TOTAL];   // rank r -> discardDst | splitSrc<<16
__device__ int           g_minCnt[NB];
__device__ int           g_maskKind;

// ---------------- helpers ----------------
__device__ __forceinline__ void tf32split(float v, uint32_t& hi, uint32_t& lo){
    asm("cvt.rna.tf32.f32 %0, %1;" : "=r"(hi) : "f"(v));
    float l = v - __uint_as_float(hi);
    asm("cvt.rna.tf32.f32 %0, %1;" : "=r"(lo) : "f"(l));
}
__device__ __forceinline__ void mma8(float* d, const uint32_t* a, const uint32_t* b){
    asm volatile("mma.sync.aligned.m16n8k8.row.col.f32.tf32.tf32.f32 "
        "{%0,%1,%2,%3}, {%4,%5,%6,%7}, {%8,%9}, {%0,%1,%2,%3};"
        : "+f"(d[0]),"+f"(d[1]),"+f"(d[2]),"+f"(d[3])
        : "r"(a[0]),"r"(a[1]),"r"(a[2]),"r"(a[3]), "r"(b[0]),"r"(b[1]));
}

// ---------------- mask dtype probe ----------------
__global__ void kProbe(const unsigned char* __restrict__ m)
{
    __shared__ int cA, c3;
    int tid = threadIdx.x;
    if (tid == 0) { cA = 0; c3 = 0; }
    __syncthreads();
    int la = 0, l3 = 0;
    for (int i = tid; i < 4096; i += 256) {
        unsigned char v = m[i];
        if ((i & 3) == 1 && v) la++;
        if ((i & 3) == 3 && v == 0x3F) l3++;
    }
    atomicAdd(&cA, la); atomicAdd(&c3, l3);
    __syncthreads();
    if (tid == 0) g_maskKind = (cA > 0) ? 0 : ((c3 > 0) ? 1 : 2);
}

// ---------------- K1: gate GEMM via mma.sync 3xTF32, fused relu/w2/sigmoid ----------------
// CTA: 128 tokens x 128 H. 8 warps: warpM=wid&3 (32 rows), warpN=wid>>2 (64 cols).
__global__ __launch_bounds__(256) void kLogitM(
    const float* __restrict__ x,  const float* __restrict__ w1,
    const float* __restrict__ b1, const float* __restrict__ w2,
    const float* __restrict__ b2)
{
    extern __shared__ float sm[];
    float* Ah = sm;
    float* Al = Ah + 128*STR;
    float* Bh = Al + 128*STR;
    float* Bl = Bh + 128*STR;
    float* b1s = Bl + 128*STR;   // 128
    float* w2s = b1s + 128;      // 128
    float* sLog = w2s + 128;     // 128

    int tid = threadIdx.x, wid = tid >> 5, lane = tid & 31;
    int warpM = wid & 3, warpN = wid >> 2;
    int tileBase = blockIdx.x * 128;
    if (tid < 128) { b1s[tid] = b1[tid]; w2s[tid] = w2[tid]; sLog[tid] = 0.f; }

    float acc[2][8][4];
    #pragma unroll
    for (int mt = 0; mt < 2; mt++)
        #pragma unroll
        for (int nt = 0; nt < 8; nt++)
            #pragma unroll
            for (int q = 0; q < 4; q++) acc[mt][nt][q] = 0.f;

    const float4* xf4 = (const float4*)x;
    const float4* w1f4 = (const float4*)w1;

    for (int c = 0; c < 8; c++) {
        int k0 = c * 32;
        __syncthreads();
        // fill A: 128 x 32, hi/lo
        #pragma unroll
        for (int t = 0; t < 4; t++) {
            int i = tid + t * 256, r = i >> 3, j = i & 7;
            float4 v = xf4[(size_t)(tileBase + r) * 64 + (k0 >> 2) + j];
            uint32_t hx,lx,hy,ly,hz,lz,hw,lw;
            tf32split(v.x,hx,lx); tf32split(v.y,hy,ly);
            tf32split(v.z,hz,lz); tf32split(v.w,hw,lw);
            float4 hv = make_float4(__uint_as_float(hx),__uint_as_float(hy),__uint_as_float(hz),__uint_as_float(hw));
            float4 lv = make_float4(__uint_as_float(lx),__uint_as_float(ly),__uint_as_float(lz),__uint_as_float(lw));
            *(float4*)(Ah + r*STR + j*4) = hv;
            *(float4*)(Al + r*STR + j*4) = lv;
        }
        // fill B: w1 slice -> B[n=h][k], 128 x 32
        #pragma unroll
        for (int t = 0; t < 4; t++) {
            int i = tid + t * 256;           // over 1024 float4
            int kl = i >> 5, h4 = (i & 31) * 4;
            float4 v = w1f4[(size_t)(k0 + kl) * 32 + (i & 31)];
            uint32_t h, l;
            tf32split(v.x,h,l); Bh[(h4+0)*STR+kl]=__uint_as_float(h); Bl[(h4+0)*STR+kl]=__uint_as_float(l);
            tf32split(v.y,h,l); Bh[(h4+1)*STR+kl]=__uint_as_float(h); Bl[(h4+1)*STR+kl]=__uint_as_float(l);
            tf32split(v.z,h,l); Bh[(h4+2)*STR+kl]=__uint_as_float(h); Bl[(h4+2)*STR+kl]=__uint_as_float(l);
            tf32split(v.w,h,l); Bh[(h4+3)*STR+kl]=__uint_as_float(h); Bl[(h4+3)*STR+kl]=__uint_as_float(l);
        }
        __syncthreads();

        #pragma unroll
        for (int ks = 0; ks < 4; ks++) {
            int kk = ks * 8;
            uint32_t aH[2][4], aL[2][4];
            #pragma unroll
            for (int mt = 0; mt < 2; mt++) {
                int rb = warpM*32 + mt*16 + (lane >> 2);
                int cc = kk + (lane & 3);
                aH[mt][0] = __float_as_uint(Ah[rb*STR + cc]);
                aH[mt][1] = __float_as_uint(Ah[(rb+8)*STR + cc]);
                aH[mt][2] = __float_as_uint(Ah[rb*STR + cc + 4]);
                aH[mt][3] = __float_as_uint(Ah[(rb+8)*STR + cc + 4]);
                aL[mt][0] = __float_as_uint(Al[rb*STR + cc]);
                aL[mt][1] = __float_as_uint(Al[(rb+8)*STR + cc]);
                aL[mt][2] = __float_as_uint(Al[rb*STR + cc + 4]);
                aL[mt][3] = __float_as_uint(Al[(rb+8)*STR + cc + 4]);
            }
            #pragma unroll
            for (int nt = 0; nt < 8; nt++) {
                int nb = warpN*64 + nt*8 + (lane >> 2);
                int kr = kk + (lane & 3);
                uint32_t bH[2], bL[2];
                bH[0] = __float_as_uint(Bh[nb*STR + kr]);
                bH[1] = __float_as_uint(Bh[nb*STR + kr + 4]);
                bL[0] = __float_as_uint(Bl[nb*STR + kr]);
                bL[1] = __float_as_uint(Bl[nb*STR + kr + 4]);
                #pragma unroll
                for (int mt = 0; mt < 2; mt++) {
                    mma8(acc[mt][nt], aH[mt], bH);
                    mma8(acc[mt][nt], aH[mt], bL);
                    mma8(acc[mt][nt], aL[mt], bH);
                }
            }
        }
    }
    __syncthreads();

    // epilogue: relu(h + b1) * w2, reduce over 128 cols -> logit -> sigmoid
    #pragma unroll
    for (int mt = 0; mt < 2; mt++) {
        float p0 = 0.f, p1 = 0.f;
        #pragma unroll
        for (int nt = 0; nt < 8; nt++) {
            int c0 = warpN*64 + nt*8 + (lane & 3)*2, c1 = c0 + 1;
            p0 += fmaxf(acc[mt][nt][0] + b1s[c0], 0.f) * w2s[c0]
                + fmaxf(acc[mt][nt][1] + b1s[c1], 0.f) * w2s[c1];
            p1 += fmaxf(acc[mt][nt][2] + b1s[c0], 0.f) * w2s[c0]
                + fmaxf(acc[mt][nt][3] + b1s[c1], 0.f) * w2s[c1];
        }
        p0 += __shfl_xor_sync(0xffffffffu, p0, 1); p0 += __shfl_xor_sync(0xffffffffu, p0, 2);
        p1 += __shfl_xor_sync(0xffffffffu, p1, 1); p1 += __shfl_xor_sync(0xffffffffu, p1, 2);
        if ((lane & 3) == 0) {
            int r = warpM*32 + mt*16 + (lane >> 2);
            atomicAdd(sLog + r, p0);
            atomicAdd(sLog + r + 8, p1);
        }
    }
    __syncthreads();
    if (tid < 128) {
        float logit = sLog[tid] + b2[0];
        g_sig[tileBase + tid] = 1.0f / (1.0f + expf(-logit));
    }
}

// ---------------- block exclusive scan over 4096 packed ints ----------------
__device__ __forceinline__ void scan4096(int* A)
{
    __shared__ int wS[8];
    int tid = threadIdx.x;
    int base = tid * 16;
    int loc[16]; int sum = 0;
    #pragma unroll
    for (int i = 0; i < 16; i++) { int v = A[base + i]; loc[i] = sum; sum += v; }
    int lane = tid & 31, w = tid >> 5;
    int inc = sum;
    #pragma unroll
    for (int off = 1; off < 32; off <<= 1) {
        int t = __shfl_up_sync(0xffffffffu, inc, off);
        if (lane >= off) inc += t;
    }
    if (lane == 31) wS[w] = inc;
    __syncthreads();
    if (tid == 0) { int run = 0; for (int i = 0; i < 8; i++) { int t = wS[i]; wS[i] = run; run += t; } }
    __syncthreads();
    int off = wS[w] + (inc - sum);
    #pragma unroll
    for (int i = 0; i < 16; i++) A[base + i] = off + loc[i];
    __syncthreads();
}

// ---------------- K2: per-batch selection ----------------
__global__ __launch_bounds__(256,1) void kSelect(const void* __restrict__ maskraw)
{
    __shared__ unsigned int keys[NTOK];
    __shared__ unsigned char cat[NTOK];
    __shared__ int sIdx[NTOK];
    __shared__ int hist[256];
    __shared__ unsigned int sPfx;
    __shared__ int sKK, sC1, sC2;

    int b = blockIdx.x, tid = threadIdx.x;
    if (tid == 0) { sC1 = 0; sC2 = 0; }
    __syncthreads();

    int kind = g_maskKind;
    int lc1 = 0, lc2 = 0;
    for (int n = tid; n < NTOK; n += 256) {
        float s = g_sig[n*NB + b];
        bool mv;
        if (kind == 0)      mv = ((const unsigned char*)maskraw)[b*NTOK + n] != 0;
        else if (kind == 1) mv = ((const float*)maskraw)[b*NTOK + n] != 0.0f;
        else                mv = ((const int*)maskraw)[b*NTOK + n] != 0;
        unsigned char c = 0;
        if (!mv) c = (s >= 0.5f) ? 1 : 2;
        cat[n] = c; keys[n] = __float_as_uint(s);
        if (c == 1) lc1++; else if (c == 2) lc2++;
    }
    atomicAdd(&sC1, lc1); atomicAdd(&sC2, lc2);
    __syncthreads();
    int kcnt = min(sC1, sC2);

    if (kcnt == 0) {
        for (int n = tid; n < NTOK; n += 256) g_cat[n*NB + b] = 0;
        if (tid == 0) g_minCnt[b] = 0;
        return;
    }

    unsigned int thr[2]; int kkEq[2];
    for (int c = 1; c <= 2; c++) {
        unsigned int pfx = 0; int kk = kcnt;
        for (int p = 24; p >= 0; p -= 8) {
            hist[tid] = 0;
            __syncthreads();
            for (int n = tid; n < NTOK; n += 256) {
                if (cat[n] == (unsigned char)c) {
                    unsigned int u = keys[n];
                    if ((((unsigned long long)(u ^ pfx)) >> (p + 8)) == 0ull)
                        atomicAdd(&hist[(u >> p) & 255], 1);
                }
            }
            __syncthreads();
            if (tid == 0) {
                int cum = 0;
                for (int d = 255; d >= 0; d--) {
                    cum += hist[d];
                    if (cum >= kk) { sPfx = pfx | ((unsigned)d << p); sKK = kk - (cum - hist[d]); break; }
                }
            }
            __syncthreads();
            pfx = sPfx; kk = sKK;
            __syncthreads();
        }
        thr[c-1] = pfx; kkEq[c-1] = kk;
    }

    for (int n = tid; n < NTOK; n += 256) {
        int f = 0;
        if (cat[n] == 1 && keys[n] == thr[0]) f = 1;
        if (cat[n] == 2 && keys[n] == thr[1]) f |= 1 << 16;
        sIdx[n] = f;
    }
    __syncthreads();
    scan4096(sIdx);

    for (int n = tid; n < NTOK; n += 256) {
        unsigned char c = cat[n], c2 = 0;
        if (c == 1) {
            if (keys[n] > thr[0] || (keys[n] == thr[0] && (sIdx[n] & 0xffff) < kkEq[0])) c2 = 1;
        } else if (c == 2) {
            if (keys[n] > thr[1] || (keys[n] == thr[1] && (sIdx[n] >> 16) < kkEq[1])) c2 = 2;
        }
        cat[n] = c2;
    }
    __syncthreads();

    for (int n = tid; n < NTOK; n += 256)
        keys[n] = (unsigned)((cat[n] == 1 ? 1 : 0) | ((cat[n] == 2 ? 1 : 0) << 16));
    __syncthreads();
    scan4096((int*)keys);

    for (int n = tid; n < NTOK; n += 256)
        if (cat[n] == 1) sIdx[(int)(keys[n] & 0xffff)] = n;
    __syncthreads();

    for (int n = tid; n < NTOK; n += 256) {
        g_cat[n*NB + b] = cat[n];
        if (cat[n] == 1) {
            int r = (int)(keys[n] & 0xffff);
            g_splitWork[b*NTOK + r] = n | (n << 16);
        } else if (cat[n] == 2) {
            int r = (int)(keys[n] >> 16);
            g_pairWork[b*NTOK + r] = n | (sIdx[r] << 16);
        }
    }
    if (tid == 0) g_minCnt[b] = kcnt;
}

// ---------------- K3: selective z GEMM via mma.sync 3xTF32 ----------------
// Grid (rowtile, batch, ct 0..3): ct*128 = global z col base; half = ct>>1.
// A = gathered split-source rows (same list for both halves); scatter with bias+relu.
__global__ __launch_bounds__(256) void kZM(
    const float* __restrict__ x, const float* __restrict__ ws,
    const float* __restrict__ bs, float* __restrict__ out)
{
    int b = blockIdx.y, ct = blockIdx.z, half = ct >> 1;
    int rows = g_minCnt[b];
    int r0 = blockIdx.x * 128;
    if (r0 >= rows) return;

    extern __shared__ float sm[];
    float* Ah = sm;
    float* Al = Ah + 128*STR;
    float* Bh = Al + 128*STR;
    float* Bl = Bh + 128*STR;
    float* biasl = Bl + 128*STR;        // 128
    int*   srcs  = (int*)(biasl + 128); // 128
    int*   dsts  = srcs + 128;          // 128

    int tid = threadIdx.x, wid = tid >> 5, lane = tid & 31;
    int warpM = wid & 3, warpN = wid >> 2;
    int nr = min(128, rows - r0);

    if (tid < 128) {
        biasl[tid] = bs[ct * 128 + tid];
        if (tid < nr) {
            srcs[tid] = g_splitWork[b*NTOK + r0 + tid] & 0xffff;
            dsts[tid] = (half ? g_pairWork : g_splitWork)[b*NTOK + r0 + tid] & 0xffff;
        } else { srcs[tid] = 0; dsts[tid] = -1; }
    }

    float acc[2][8][4];
    #pragma unroll
    for (int mt = 0; mt < 2; mt++)
        #pragma unroll
        for (int nt = 0; nt < 8; nt++)
            #pragma unroll
            for (int q = 0; q < 4; q++) acc[mt][nt][q] = 0.f;

    const float4* xf4 = (const float4*)x;
    const float4* wsf4 = (const float4*)ws;

    for (int c = 0; c < 8; c++) {
        int k0 = c * 32;
        __syncthreads();
        #pragma unroll
        for (int t = 0; t < 4; t++) {
            int i = tid + t * 256, r = i >> 3, j = i & 7;
            int src = srcs[r];
            float4 v = xf4[(size_t)(src * NB + b) * 64 + (k0 >> 2) + j];
            uint32_t hx,lx,hy,ly,hz,lz,hw,lw;
            tf32split(v.x,hx,lx); tf32split(v.y,hy,ly);
            tf32split(v.z,hz,lz); tf32split(v.w,hw,lw);
            float4 hv = make_float4(__uint_as_float(hx),__uint_as_float(hy),__uint_as_float(hz),__uint_as_float(hw));
            float4 lv = make_float4(__uint_as_float(lx),__uint_as_float(ly),__uint_as_float(lz),__uint_as_float(lw));
            *(float4*)(Ah + r*STR + j*4) = hv;
            *(float4*)(Al + r*STR + j*4) = lv;
        }
        #pragma unroll
        for (int t = 0; t < 4; t++) {
            int i = tid + t * 256;
            int kl = i >> 5, h4 = (i & 31) * 4;
            float4 v = wsf4[(size_t)(k0 + kl) * 128 + ct * 32 + (i & 31)];
            uint32_t h, l;
            tf32split(v.x,h,l); Bh[(h4+0)*STR+kl]=__uint_as_float(h); Bl[(h4+0)*STR+kl]=__uint_as_float(l);
            tf32split(v.y,h,l); Bh[(h4+1)*STR+kl]=__uint_as_float(h); Bl[(h4+1)*STR+kl]=__uint_as_float(l);
            tf32split(v.z,h,l); Bh[(h4+2)*STR+kl]=__uint_as_float(h); Bl[(h4+2)*STR+kl]=__uint_as_float(l);
            tf32split(v.w,h,l); Bh[(h4+3)*STR+kl]=__uint_as_float(h); Bl[(h4+3)*STR+kl]=__uint_as_float(l);
        }
        __syncthreads();

        #pragma unroll
        for (int ks = 0; ks < 4; ks++) {
            int kk = ks * 8;
            uint32_t aH[2][4], aL[2][4];
            #pragma unroll
            for (int mt = 0; mt < 2; mt++) {
                int rb = warpM*32 + mt*16 + (lane >> 2);
                int cc = kk + (lane & 3);
                aH[mt][0] = __float_as_uint(Ah[rb*STR + cc]);
                aH[mt][1] = __float_as_uint(Ah[(rb+8)*STR + cc]);
                aH[mt][2] = __float_as_uint(Ah[rb*STR + cc + 4]);
                aH[mt][3] = __float_as_uint(Ah[(rb+8)*STR + cc + 4]);
                aL[mt][0] = __float_as_uint(Al[rb*STR + cc]);
                aL[mt][1] = __float_as_uint(Al[(rb+8)*STR + cc]);
                aL[mt][2] = __float_as_uint(Al[rb*STR + cc + 4]);
                aL[mt][3] = __float_as_uint(Al[(rb+8)*STR + cc + 4]);
            }
            #pragma unroll
            for (int nt = 0; nt < 8; nt++) {
                int nb = warpN*64 + nt*8 + (lane >> 2);
                int kr = kk + (lane & 3);
                uint32_t bH[2], bL[2];
                bH[0] = __float_as_uint(Bh[nb*STR + kr]);
                bH[1] = __float_as_uint(Bh[nb*STR + kr + 4]);
                bL[0] = __float_as_uint(Bl[nb*STR + kr]);
                bL[1] = __float_as_uint(Bl[nb*STR + kr + 4]);
                #pragma unroll
                for (int mt = 0; mt < 2; mt++) {
                    mma8(acc[mt][nt], aH[mt], bH);
                    mma8(acc[mt][nt], aH[mt], bL);
                    mma8(acc[mt][nt], aL[mt], bH);
                }
            }
        }
    }
    __syncthreads();

    // scatter epilogue
    int outColBase = (ct & 1) * 128;
    #pragma unroll
    for (int mt = 0; mt < 2; mt++) {
        int rA = warpM*32 + mt*16 + (lane >> 2);
        int d0 = dsts[rA], d1 = dsts[rA + 8];
        #pragma unroll
        for (int nt = 0; nt < 8; nt++) {
            int c0 = warpN*64 + nt*8 + (lane & 3)*2;
            float bb0 = biasl[c0], bb1 = biasl[c0+1];
            if (d0 >= 0) {
                float2 o; o.x = fmaxf(acc[mt][nt][0] + bb0, 0.f);
                          o.y = fmaxf(acc[mt][nt][1] + bb1, 0.f);
                *(float2*)(out + (size_t)(d0*NB + b)*NC + outColBase + c0) = o;
            }
            if (d1 >= 0) {
                float2 o; o.x = fmaxf(acc[mt][nt][2] + bb0, 0.f);
                          o.y = fmaxf(acc[mt][nt][3] + bb1, 0.f);
                *(float2*)(out + (size_t)(d1*NB + b)*NC + outColBase + c0) = o;
            }
        }
    }
}

// ---------------- K4: passthrough copy ----------------
__global__ void kCopy(const float* __restrict__ x, float* __restrict__ out)
{
    int idx = blockIdx.x * 256 + threadIdx.x;
    int t = idx >> 6;
    if (g_cat[t] == 0)
        ((float4*)out)[idx] = ((const float4*)x)[idx];
}

// ---------------- launch ----------------
extern "C" void kernel_launch(void* const* d_in, const int* in_sizes, int n_in,
                              void* d_out, int out_size)
{
    const float* x  = (const float*)d_in[0];
    const void*  mk = d_in[1];
    const float* w1 = (const float*)d_in[2];
    const float* b1 = (const float*)d_in[3];
    const float* w2 = (const float*)d_in[4];
    const float* b2 = (const float*)d_in[5];
    const float* ws = (const float*)d_in[6];
    const float* bs = (const float*)d_in[7];
    float* out = (float*)d_out;

    const int SMEM = 4*128*STR*4 + 2048;   // 73728 + pad = 75776
    cudaFuncSetAttribute(kLogitM, cudaFuncAttributeMaxDynamicSharedMemorySize, SMEM);
    cudaFuncSetAttribute(kZM,     cudaFuncAttributeMaxDynamicSharedMemorySize, SMEM);

    kProbe<<<1, 256>>>((const unsigned char*)mk);
    kLogitM<<<TOTAL/128, 256, SMEM>>>(x, w1, b1, w2, b2);
    kSelect<<<NB, 256>>>(mk);
    dim3 gz(16, NB, 4);
    kZM<<<gz, 256, SMEM>>>(x, ws, bs, out);
    kCopy<<<TOTAL/4, 256>>>(x, out);
}

// round 8
// speedup vs baseline: 1.6873x; 1.6873x over previous
#include <cuda_runtime.h>
#include <math.h>
#include <stdint.h>

#define NTOK 4096
#define NB   16
#define NC   256
#define TOTAL (NTOK*NB)
#define ASTR 36    // A smem stride (floats): bank (4r+c)%32 distinct
#define BSTR 132   // B smem stride (floats): bank (4k+n)%32 distinct
#define ABYTES (64*ASTR*4)       // 9216
#define BBYTES (32*BSTR*4)       // 16896
#define BUFBYTES (ABYTES+BBYTES) // 26112
#define SMEMREQ (2*BUFBYTES + 2048)   // tail region needs 1280B (kLogitM) / 1024B (kZM)

// ---------------- device scratch ----------------
__device__ float         g_sig[TOTAL];
__device__ unsigned char g_cat[TOTAL];
__device__ int           g_splitWork[TOTAL];
__device__ int           g_pairWork[TOTAL];
__device__ int           g_minCnt[NB];
__device__ int           g_maskKind;

// ---------------- helpers ----------------
__device__ __forceinline__ uint32_t smem_u32(const void* p){
    uint32_t a;
    asm("{ .reg .u64 t; cvta.to.shared.u64 t, %1; cvt.u32.u64 %0, t; }" : "=r"(a) : "l"(p));
    return a;
}
__device__ __forceinline__ void tf32split(float v, uint32_t& hi, uint32_t& lo){
    asm("cvt.rna.tf32.f32 %0, %1;" : "=r"(hi) : "f"(v));
    float l = v - __uint_as_float(hi);
    asm("cvt.rna.tf32.f32 %0, %1;" : "=r"(lo) : "f"(l));
}
__device__ __forceinline__ void mma8(float* d, const uint32_t* a, const uint32_t* b){
    asm volatile("mma.sync.aligned.m16n8k8.row.col.f32.tf32.tf32.f32 "
        "{%0,%1,%2,%3}, {%4,%5,%6,%7}, {%8,%9}, {%0,%1,%2,%3};"
        : "+f"(d[0]),"+f"(d[1]),"+f"(d[2]),"+f"(d[3])
        : "r"(a[0]),"r"(a[1]),"r"(a[2]),"r"(a[3]), "r"(b[0]),"r"(b[1]));
}
#define CP16(dst, src) asm volatile("cp.async.cg.shared.global [%0], [%1], 16;" :: "r"(dst), "l"(src))
#define CPCOMMIT()     asm volatile("cp.async.commit_group;" ::: "memory")
#define CPWAIT1()      asm volatile("cp.async.wait_group 1;" ::: "memory")
#define CPWAIT0()      asm volatile("cp.async.wait_group 0;" ::: "memory")

// ---------------- mask dtype probe ----------------
__global__ void kProbe(const unsigned char* __restrict__ m)
{
    __shared__ int cA, c3;
    int tid = threadIdx.x;
    if (tid == 0) { cA = 0; c3 = 0; }
    __syncthreads();
    int la = 0, l3 = 0;
    for (int i = tid; i < 4096; i += 256) {
        unsigned char v = m[i];
        if ((i & 3) == 1 && v) la++;
        if ((i & 3) == 3 && v == 0x3F) l3++;
    }
    atomicAdd(&cA, la); atomicAdd(&c3, l3);
    __syncthreads();
    if (tid == 0) g_maskKind = (cA > 0) ? 0 : ((c3 > 0) ? 1 : 2);
}

// =======================================================================
// Shared compute core: 64x128 tile, 4 warps (warpM=wid&1, warpN=wid>>1),
// warp tile 32x64, m16n8k8 3xTF32, split-at-fragment-load.
// =======================================================================
__device__ __forceinline__ void computeChunk(
    const float* As, const float* Bs, int warpM, int warpN, int lane,
    float acc[2][8][4])
{
    #pragma unroll
    for (int ks = 0; ks < 4; ks++) {
        int kk = ks * 8;
        uint32_t aH[2][4], aL[2][4];
        #pragma unroll
        for (int mt = 0; mt < 2; mt++) {
            int rb = warpM*32 + mt*16 + (lane >> 2);
            int cc = kk + (lane & 3);
            tf32split(As[rb*ASTR + cc],        aH[mt][0], aL[mt][0]);
            tf32split(As[(rb+8)*ASTR + cc],    aH[mt][1], aL[mt][1]);
            tf32split(As[rb*ASTR + cc + 4],    aH[mt][2], aL[mt][2]);
            tf32split(As[(rb+8)*ASTR + cc + 4],aH[mt][3], aL[mt][3]);
        }
        #pragma unroll
        for (int nt = 0; nt < 8; nt++) {
            int nb = warpN*64 + nt*8 + (lane >> 2);
            int kr = kk + (lane & 3);
            uint32_t bH[2], bL[2];
            tf32split(Bs[kr*BSTR + nb],       bH[0], bL[0]);
            tf32split(Bs[(kr+4)*BSTR + nb],   bH[1], bL[1]);
            #pragma unroll
            for (int mt = 0; mt < 2; mt++) {
                mma8(acc[mt][nt], aH[mt], bH);
                mma8(acc[mt][nt], aH[mt], bL);
                mma8(acc[mt][nt], aL[mt], bH);
            }
        }
    }
}

// ---------------- K1: gate GEMM, fused relu/w2/sigmoid ----------------
__global__ __launch_bounds__(128) void kLogitM(
    const float* __restrict__ x,  const float* __restrict__ w1,
    const float* __restrict__ b1, const float* __restrict__ w2,
    const float* __restrict__ b2)
{
    extern __shared__ float smf[];
    uint32_t sb = smem_u32(smf);
    float* b1s = smf + 2*BUFBYTES/4;
    float* w2s = b1s + 128;
    float* sLog = w2s + 128;           // 64
    int tid = threadIdx.x, wid = tid >> 5, lane = tid & 31;
    int warpM = wid & 1, warpN = wid >> 1;
    int tileBase = blockIdx.x * 64;

    b1s[tid] = b1[tid]; w2s[tid] = w2[tid];
    if (tid < 64) sLog[tid] = 0.f;

    float acc[2][8][4];
    #pragma unroll
    for (int mt = 0; mt < 2; mt++)
        #pragma unroll
        for (int nt = 0; nt < 8; nt++)
            #pragma unroll
            for (int q = 0; q < 4; q++) acc[mt][nt][q] = 0.f;

    auto issue = [&](int c, int buf){
        int k0 = c * 32;
        uint32_t ab = sb + buf * BUFBYTES;
        #pragma unroll
        for (int t = 0; t < 4; t++) {
            int s = tid + t*128, r = s >> 3, seg = s & 7;
            CP16(ab + r*(ASTR*4) + seg*16,
                 x + (size_t)(tileBase + r)*NC + k0 + seg*4);
        }
        uint32_t bb = sb + buf * BUFBYTES + ABYTES;
        #pragma unroll
        for (int t = 0; t < 8; t++) {
            int s = tid + t*128, k = s >> 5, seg = s & 31;
            CP16(bb + k*(BSTR*4) + seg*16,
                 w1 + (size_t)(k0 + k)*128 + seg*4);
        }
    };

    issue(0, 0); CPCOMMIT();
    for (int c = 0; c < 8; c++) {
        if (c < 7) { issue(c+1, (c+1)&1); CPCOMMIT(); CPWAIT1(); }
        else CPWAIT0();
        __syncthreads();
        const float* As = smf + (c&1)*(BUFBYTES/4);
        const float* Bs = As + ABYTES/4;
        computeChunk(As, Bs, warpM, warpN, lane, acc);
        __syncthreads();
    }

    // epilogue: relu(h + b1) * w2 reduced over 128 cols -> sigmoid
    #pragma unroll
    for (int mt = 0; mt < 2; mt++) {
        float p0 = 0.f, p1 = 0.f;
        #pragma unroll
        for (int nt = 0; nt < 8; nt++) {
            int c0 = warpN*64 + nt*8 + (lane & 3)*2, c1 = c0 + 1;
            p0 += fmaxf(acc[mt][nt][0] + b1s[c0], 0.f) * w2s[c0]
                + fmaxf(acc[mt][nt][1] + b1s[c1], 0.f) * w2s[c1];
            p1 += fmaxf(acc[mt][nt][2] + b1s[c0], 0.f) * w2s[c0]
                + fmaxf(acc[mt][nt][3] + b1s[c1], 0.f) * w2s[c1];
        }
        p0 += __shfl_xor_sync(0xffffffffu, p0, 1); p0 += __shfl_xor_sync(0xffffffffu, p0, 2);
        p1 += __shfl_xor_sync(0xffffffffu, p1, 1); p1 += __shfl_xor_sync(0xffffffffu, p1, 2);
        if ((lane & 3) == 0) {
            int r = warpM*32 + mt*16 + (lane >> 2);
            atomicAdd(sLog + r, p0);
            atomicAdd(sLog + r + 8, p1);
        }
    }
    __syncthreads();
    if (tid < 64) {
        float logit = sLog[tid] + b2[0];
        g_sig[tileBase + tid] = 1.0f / (1.0f + expf(-logit));
    }
}

// ---------------- block exclusive scan over 4096 packed ints ----------------
__device__ __forceinline__ void scan4096(int* A)
{
    __shared__ int wS[8];
    int tid = threadIdx.x;
    int base = tid * 16;
    int loc[16]; int sum = 0;
    #pragma unroll
    for (int i = 0; i < 16; i++) { int v = A[base + i]; loc[i] = sum; sum += v; }
    int lane = tid & 31, w = tid >> 5;
    int inc = sum;
    #pragma unroll
    for (int off = 1; off < 32; off <<= 1) {
        int t = __shfl_up_sync(0xffffffffu, inc, off);
        if (lane >= off) inc += t;
    }
    if (lane == 31) wS[w] = inc;
    __syncthreads();
    if (tid == 0) { int run = 0; for (int i = 0; i < 8; i++) { int t = wS[i]; wS[i] = run; run += t; } }
    __syncthreads();
    int off = wS[w] + (inc - sum);
    #pragma unroll
    for (int i = 0; i < 16; i++) A[base + i] = off + loc[i];
    __syncthreads();
}

// ---------------- K2: per-batch selection ----------------
__global__ __launch_bounds__(256,1) void kSelect(const void* __restrict__ maskraw)
{
    __shared__ unsigned int keys[NTOK];
    __shared__ unsigned char cat[NTOK];
    __shared__ int sIdx[NTOK];
    __shared__ int hist[256];
    __shared__ unsigned int sPfx;
    __shared__ int sKK, sC1, sC2;

    int b = blockIdx.x, tid = threadIdx.x;
    if (tid == 0) { sC1 = 0; sC2 = 0; }
    __syncthreads();

    int kind = g_maskKind;
    int lc1 = 0, lc2 = 0;
    for (int n = tid; n < NTOK; n += 256) {
        float s = g_sig[n*NB + b];
        bool mv;
        if (kind == 0)      mv = ((const unsigned char*)maskraw)[b*NTOK + n] != 0;
        else if (kind == 1) mv = ((const float*)maskraw)[b*NTOK + n] != 0.0f;
        else                mv = ((const int*)maskraw)[b*NTOK + n] != 0;
        unsigned char c = 0;
        if (!mv) c = (s >= 0.5f) ? 1 : 2;
        cat[n] = c; keys[n] = __float_as_uint(s);
        if (c == 1) lc1++; else if (c == 2) lc2++;
    }
    atomicAdd(&sC1, lc1); atomicAdd(&sC2, lc2);
    __syncthreads();
    int kcnt = min(sC1, sC2);

    if (kcnt == 0) {
        for (int n = tid; n < NTOK; n += 256) g_cat[n*NB + b] = 0;
        if (tid == 0) g_minCnt[b] = 0;
        return;
    }

    unsigned int thr[2]; int kkEq[2];
    for (int c = 1; c <= 2; c++) {
        unsigned int pfx = 0; int kk = kcnt;
        for (int p = 24; p >= 0; p -= 8) {
            hist[tid] = 0;
            __syncthreads();
            for (int n = tid; n < NTOK; n += 256) {
                if (cat[n] == (unsigned char)c) {
                    unsigned int u = keys[n];
                    if ((((unsigned long long)(u ^ pfx)) >> (p + 8)) == 0ull)
                        atomicAdd(&hist[(u >> p) & 255], 1);
                }
            }
            __syncthreads();
            if (tid == 0) {
                int cum = 0;
                for (int d = 255; d >= 0; d--) {
                    cum += hist[d];
                    if (cum >= kk) { sPfx = pfx | ((unsigned)d << p); sKK = kk - (cum - hist[d]); break; }
                }
            }
            __syncthreads();
            pfx = sPfx; kk = sKK;
            __syncthreads();
        }
        thr[c-1] = pfx; kkEq[c-1] = kk;
    }

    for (int n = tid; n < NTOK; n += 256) {
        int f = 0;
        if (cat[n] == 1 && keys[n] == thr[0]) f = 1;
        if (cat[n] == 2 && keys[n] == thr[1]) f |= 1 << 16;
        sIdx[n] = f;
    }
    __syncthreads();
    scan4096(sIdx);

    for (int n = tid; n < NTOK; n += 256) {
        unsigned char c = cat[n], c2 = 0;
        if (c == 1) {
            if (keys[n] > thr[0] || (keys[n] == thr[0] && (sIdx[n] & 0xffff) < kkEq[0])) c2 = 1;
        } else if (c == 2) {
            if (keys[n] > thr[1] || (keys[n] == thr[1] && (sIdx[n] >> 16) < kkEq[1])) c2 = 2;
        }
        cat[n] = c2;
    }
    __syncthreads();

    for (int n = tid; n < NTOK; n += 256)
        keys[n] = (unsigned)((cat[n] == 1 ? 1 : 0) | ((cat[n] == 2 ? 1 : 0) << 16));
    __syncthreads();
    scan4096((int*)keys);

    for (int n = tid; n < NTOK; n += 256)
        if (cat[n] == 1) sIdx[(int)(keys[n] & 0xffff)] = n;
    __syncthreads();

    for (int n = tid; n < NTOK; n += 256) {
        g_cat[n*NB + b] = cat[n];
        if (cat[n] == 1) {
            int r = (int)(keys[n] & 0xffff);
            g_splitWork[b*NTOK + r] = n | (n << 16);
        } else if (cat[n] == 2) {
            int r = (int)(keys[n] >> 16);
            g_pairWork[b*NTOK + r] = n | (sIdx[r] << 16);
        }
    }
    if (tid == 0) g_minCnt[b] = kcnt;
}

// ---------------- K3: selective z GEMM, gathered A, scattered epilogue ----------------
// Grid (rowtile(64), batch, ct 0..3). half = ct>>1.
__global__ __launch_bounds__(128) void kZM(
    const float* __restrict__ x, const float* __restrict__ ws,
    const float* __restrict__ bs, float* __restrict__ out)
{
    int b = blockIdx.y, ct = blockIdx.z, half = ct >> 1;
    int rows = g_minCnt[b];
    int r0 = blockIdx.x * 64;
    if (r0 >= rows) return;

    extern __shared__ float smf[];
    uint32_t sb = smem_u32(smf);
    float* biasl = smf + 2*BUFBYTES/4;     // 128
    int*   srcs  = (int*)(biasl + 128);    // 64
    int*   dsts  = srcs + 64;              // 64
    int tid = threadIdx.x, wid = tid >> 5, lane = tid & 31;
    int warpM = wid & 1, warpN = wid >> 1;
    int nr = min(64, rows - r0);

    biasl[tid] = bs[ct * 128 + tid];
    if (tid < 64) {
        if (tid < nr) {
            srcs[tid] = g_splitWork[b*NTOK + r0 + tid] & 0xffff;
            dsts[tid] = (half ? g_pairWork : g_splitWork)[b*NTOK + r0 + tid] & 0xffff;
        } else { srcs[tid] = 0; dsts[tid] = -1; }
    }
    __syncthreads();   // srcs ready before gather cp.async

    float acc[2][8][4];
    #pragma unroll
    for (int mt = 0; mt < 2; mt++)
        #pragma unroll
        for (int nt = 0; nt < 8; nt++)
            #pragma unroll
            for (int q = 0; q < 4; q++) acc[mt][nt][q] = 0.f;

    auto issue = [&](int c, int buf){
        int k0 = c * 32;
        uint32_t ab = sb + buf * BUFBYTES;
        #pragma unroll
        for (int t = 0; t < 4; t++) {
            int s = tid + t*128, r = s >> 3, seg = s & 7;
            CP16(ab + r*(ASTR*4) + seg*16,
                 x + (size_t)(srcs[r]*NB + b)*NC + k0 + seg*4);
        }
        uint32_t bb = sb + buf * BUFBYTES + ABYTES;
        #pragma unroll
        for (int t = 0; t < 8; t++) {
            int s = tid + t*128, k = s >> 5, seg = s & 31;
            CP16(bb + k*(BSTR*4) + seg*16,
                 ws + (size_t)(k0 + k)*512 + ct*128 + seg*4);
        }
    };

    issue(0, 0); CPCOMMIT();
    for (int c = 0; c < 8; c++) {
        if (c < 7) { issue(c+1, (c+1)&1); CPCOMMIT(); CPWAIT1(); }
        else CPWAIT0();
        __syncthreads();
        const float* As = smf + (c&1)*(BUFBYTES/4);
        const float* Bs = As + ABYTES/4;
        computeChunk(As, Bs, warpM, warpN, lane, acc);
        __syncthreads();
    }

    int outColBase = (ct & 1) * 128;
    #pragma unroll
    for (int mt = 0; mt < 2; mt++) {
        int rA = warpM*32 + mt*16 + (lane >> 2);
        int d0 = dsts[rA], d1 = dsts[rA + 8];
        #pragma unroll
        for (int nt = 0; nt < 8; nt++) {
            int c0 = warpN*64 + nt*8 + (lane & 3)*2;
            float bb0 = biasl[c0], bb1 = biasl[c0+1];
            if (d0 >= 0) {
                float2 o; o.x = fmaxf(acc[mt][nt][0] + bb0, 0.f);
                          o.y = fmaxf(acc[mt][nt][1] + bb1, 0.f);
                *(float2*)(out + (size_t)(d0*NB + b)*NC + outColBase + c0) = o;
            }
            if (d1 >= 0) {
                float2 o; o.x = fmaxf(acc[mt][nt][2] + bb0, 0.f);
                          o.y = fmaxf(acc[mt][nt][3] + bb1, 0.f);
                *(float2*)(out + (size_t)(d1*NB + b)*NC + outColBase + c0) = o;
            }
        }
    }
}

// ---------------- K4: passthrough copy ----------------
__global__ void kCopy(const float* __restrict__ x, float* __restrict__ out)
{
    int idx = blockIdx.x * 256 + threadIdx.x;
    int t = idx >> 6;
    if (g_cat[t] == 0)
        ((float4*)out)[idx] = ((const float4*)x)[idx];
}

// ---------------- launch ----------------
extern "C" void kernel_launch(void* const* d_in, const int* in_sizes, int n_in,
                              void* d_out, int out_size)
{
    const float* x  = (const float*)d_in[0];
    const void*  mk = d_in[1];
    const float* w1 = (const float*)d_in[2];
    const float* b1 = (const float*)d_in[3];
    const float* w2 = (const float*)d_in[4];
    const float* b2 = (const float*)d_in[5];
    const float* ws = (const float*)d_in[6];
    const float* bs = (const float*)d_in[7];
    float* out = (float*)d_out;

    cudaFuncSetAttribute(kLogitM, cudaFuncAttributeMaxDynamicSharedMemorySize, SMEMREQ);
    cudaFuncSetAttribute(kZM,     cudaFuncAttributeMaxDynamicSharedMemorySize, SMEMREQ);

    kProbe<<<1, 256>>>((const unsigned char*)mk);
    kLogitM<<<TOTAL/64, 128, SMEMREQ>>>(x, w1, b1, w2, b2);
    kSelect<<<NB, 256>>>(mk);
    dim3 gz(32, NB, 4);
    kZM<<<gz, 128, SMEMREQ>>>(x, ws, bs, out);
    kCopy<<<TOTAL/4, 256>>>(x, out);
}

// round 9
// speedup vs baseline: 2.0962x; 1.2423x over previous
#include <cuda_runtime.h>
#include <math.h>
#include <stdint.h>

#define NTOK 4096
#define NB   16
#define NC   256
#define TOTAL (NTOK*NB)
#define ASTR 36    // A smem stride (floats): bank (4r+c)%32 distinct
#define BSTR 132   // B smem stride (floats): bank (4k+n)%32 distinct
#define ABYTES (64*ASTR*4)       // 9216
#define BBYTES (32*BSTR*4)       // 16896
#define BUFBYTES (ABYTES+BBYTES) // 26112
#define SMEMREQ (2*BUFBYTES + 2048)

// ---------------- device scratch ----------------
__device__ float         g_sig[TOTAL];
__device__ unsigned char g_cat[TOTAL];
__device__ int           g_splitWork[TOTAL];
__device__ int           g_pairWork[TOTAL];
__device__ int           g_minCnt[NB];
__device__ int           g_maskKind;

// ---------------- helpers ----------------
__device__ __forceinline__ uint32_t smem_u32(const void* p){
    uint32_t a;
    asm("{ .reg .u64 t; cvta.to.shared.u64 t, %1; cvt.u32.u64 %0, t; }" : "=r"(a) : "l"(p));
    return a;
}
__device__ __forceinline__ void tf32split(float v, uint32_t& hi, uint32_t& lo){
    asm("cvt.rna.tf32.f32 %0, %1;" : "=r"(hi) : "f"(v));
    float l = v - __uint_as_float(hi);
    asm("cvt.rna.tf32.f32 %0, %1;" : "=r"(lo) : "f"(l));
}
__device__ __forceinline__ void mma8(float* d, const uint32_t* a, const uint32_t* b){
    asm volatile("mma.sync.aligned.m16n8k8.row.col.f32.tf32.tf32.f32 "
        "{%0,%1,%2,%3}, {%4,%5,%6,%7}, {%8,%9}, {%0,%1,%2,%3};"
        : "+f"(d[0]),"+f"(d[1]),"+f"(d[2]),"+f"(d[3])
        : "r"(a[0]),"r"(a[1]),"r"(a[2]),"r"(a[3]), "r"(b[0]),"r"(b[1]));
}
#define CP16(dst, src) asm volatile("cp.async.cg.shared.global [%0], [%1], 16;" :: "r"(dst), "l"(src))
#define CPCOMMIT()     asm volatile("cp.async.commit_group;" ::: "memory")
#define CPWAIT1()      asm volatile("cp.async.wait_group 1;" ::: "memory")
#define CPWAIT0()      asm volatile("cp.async.wait_group 0;" ::: "memory")

// ---------------- mask dtype probe ----------------
__global__ void kProbe(const unsigned char* __restrict__ m)
{
    __shared__ int cA, c3;
    int tid = threadIdx.x;
    if (tid == 0) { cA = 0; c3 = 0; }
    __syncthreads();
    int la = 0, l3 = 0;
    for (int i = tid; i < 4096; i += 256) {
        unsigned char v = m[i];
        if ((i & 3) == 1 && v) la++;
        if ((i & 3) == 3 && v == 0x3F) l3++;
    }
    atomicAdd(&cA, la); atomicAdd(&c3, l3);
    __syncthreads();
    if (tid == 0) g_maskKind = (cA > 0) ? 0 : ((c3 > 0) ? 1 : 2);
}

// =======================================================================
// Shared compute core: 64x128 tile, 4 warps, m16n8k8 3xTF32.
// =======================================================================
__device__ __forceinline__ void computeChunk(
    const float* As, const float* Bs, int warpM, int warpN, int lane,
    float acc[2][8][4])
{
    #pragma unroll
    for (int ks = 0; ks < 4; ks++) {
        int kk = ks * 8;
        uint32_t aH[2][4], aL[2][4];
        #pragma unroll
        for (int mt = 0; mt < 2; mt++) {
            int rb = warpM*32 + mt*16 + (lane >> 2);
            int cc = kk + (lane & 3);
            tf32split(As[rb*ASTR + cc],        aH[mt][0], aL[mt][0]);
            tf32split(As[(rb+8)*ASTR + cc],    aH[mt][1], aL[mt][1]);
            tf32split(As[rb*ASTR + cc + 4],    aH[mt][2], aL[mt][2]);
            tf32split(As[(rb+8)*ASTR + cc + 4],aH[mt][3], aL[mt][3]);
        }
        #pragma unroll
        for (int nt = 0; nt < 8; nt++) {
            int nb = warpN*64 + nt*8 + (lane >> 2);
            int kr = kk + (lane & 3);
            uint32_t bH[2], bL[2];
            tf32split(Bs[kr*BSTR + nb],       bH[0], bL[0]);
            tf32split(Bs[(kr+4)*BSTR + nb],   bH[1], bL[1]);
            #pragma unroll
            for (int mt = 0; mt < 2; mt++) {
                mma8(acc[mt][nt], aH[mt], bH);
                mma8(acc[mt][nt], aH[mt], bL);
                mma8(acc[mt][nt], aL[mt], bH);
            }
        }
    }
}

// ---------------- K1: gate GEMM, fused relu/w2/sigmoid ----------------
__global__ __launch_bounds__(128) void kLogitM(
    const float* __restrict__ x,  const float* __restrict__ w1,
    const float* __restrict__ b1, const float* __restrict__ w2,
    const float* __restrict__ b2)
{
    extern __shared__ float smf[];
    uint32_t sb = smem_u32(smf);
    float* b1s = smf + 2*BUFBYTES/4;
    float* w2s = b1s + 128;
    float* sLog = w2s + 128;           // 64
    int tid = threadIdx.x, wid = tid >> 5, lane = tid & 31;
    int warpM = wid & 1, warpN = wid >> 1;
    int tileBase = blockIdx.x * 64;

    b1s[tid] = b1[tid]; w2s[tid] = w2[tid];
    if (tid < 64) sLog[tid] = 0.f;

    float acc[2][8][4];
    #pragma unroll
    for (int mt = 0; mt < 2; mt++)
        #pragma unroll
        for (int nt = 0; nt < 8; nt++)
            #pragma unroll
            for (int q = 0; q < 4; q++) acc[mt][nt][q] = 0.f;

    auto issue = [&](int c, int buf){
        int k0 = c * 32;
        uint32_t ab = sb + buf * BUFBYTES;
        #pragma unroll
        for (int t = 0; t < 4; t++) {
            int s = tid + t*128, r = s >> 3, seg = s & 7;
            CP16(ab + r*(ASTR*4) + seg*16,
                 x + (size_t)(tileBase + r)*NC + k0 + seg*4);
        }
        uint32_t bb = sb + buf * BUFBYTES + ABYTES;
        #pragma unroll
        for (int t = 0; t < 8; t++) {
            int s = tid + t*128, k = s >> 5, seg = s & 31;
            CP16(bb + k*(BSTR*4) + seg*16,
                 w1 + (size_t)(k0 + k)*128 + seg*4);
        }
    };

    issue(0, 0); CPCOMMIT();
    for (int c = 0; c < 8; c++) {
        if (c < 7) { issue(c+1, (c+1)&1); CPCOMMIT(); CPWAIT1(); }
        else CPWAIT0();
        __syncthreads();
        const float* As = smf + (c&1)*(BUFBYTES/4);
        const float* Bs = As + ABYTES/4;
        computeChunk(As, Bs, warpM, warpN, lane, acc);
        __syncthreads();
    }

    #pragma unroll
    for (int mt = 0; mt < 2; mt++) {
        float p0 = 0.f, p1 = 0.f;
        #pragma unroll
        for (int nt = 0; nt < 8; nt++) {
            int c0 = warpN*64 + nt*8 + (lane & 3)*2, c1 = c0 + 1;
            p0 += fmaxf(acc[mt][nt][0] + b1s[c0], 0.f) * w2s[c0]
                + fmaxf(acc[mt][nt][1] + b1s[c1], 0.f) * w2s[c1];
            p1 += fmaxf(acc[mt][nt][2] + b1s[c0], 0.f) * w2s[c0]
                + fmaxf(acc[mt][nt][3] + b1s[c1], 0.f) * w2s[c1];
        }
        p0 += __shfl_xor_sync(0xffffffffu, p0, 1); p0 += __shfl_xor_sync(0xffffffffu, p0, 2);
        p1 += __shfl_xor_sync(0xffffffffu, p1, 1); p1 += __shfl_xor_sync(0xffffffffu, p1, 2);
        if ((lane & 3) == 0) {
            int r = warpM*32 + mt*16 + (lane >> 2);
            atomicAdd(sLog + r, p0);
            atomicAdd(sLog + r + 8, p1);
        }
    }
    __syncthreads();
    if (tid < 64) {
        float logit = sLog[tid] + b2[0];
        g_sig[tileBase + tid] = 1.0f / (1.0f + expf(-logit));
    }
}

// ---------------- block exclusive scan over 4096 ints, 512 threads ----------------
__device__ __forceinline__ void scan4096_512(int* A)
{
    __shared__ int wS[16];
    int tid = threadIdx.x;
    int base = tid * 8;
    int loc[8]; int sum = 0;
    #pragma unroll
    for (int i = 0; i < 8; i++) { int v = A[base + i]; loc[i] = sum; sum += v; }
    int lane = tid & 31, w = tid >> 5;
    int inc = sum;
    #pragma unroll
    for (int off = 1; off < 32; off <<= 1) {
        int t = __shfl_up_sync(0xffffffffu, inc, off);
        if (lane >= off) inc += t;
    }
    if (lane == 31) wS[w] = inc;
    __syncthreads();
    if (tid == 0) { int run = 0; for (int i = 0; i < 16; i++) { int t = wS[i]; wS[i] = run; run += t; } }
    __syncthreads();
    int off = wS[w] + (inc - sum);
    #pragma unroll
    for (int i = 0; i < 8; i++) A[base + i] = off + loc[i];
    __syncthreads();
}

// ---------------- K2: per-batch selection (512 threads, parallel digit scan) ----------------
__global__ __launch_bounds__(512,1) void kSelect(const void* __restrict__ maskraw)
{
    __shared__ unsigned int keys[NTOK];
    __shared__ unsigned char cat[NTOK];
    __shared__ int sIdx[NTOK];
    __shared__ int hist[256];
    __shared__ int sfxArr[256];
    __shared__ int wT[8];
    __shared__ unsigned int sPfx;
    __shared__ int sKK, sC1, sC2;

    int b = blockIdx.x, tid = threadIdx.x;
    int lane = tid & 31;
    if (tid == 0) { sC1 = 0; sC2 = 0; }
    __syncthreads();

    int kind = g_maskKind;
    int lc1 = 0, lc2 = 0;
    for (int n = tid; n < NTOK; n += 512) {
        float s = g_sig[n*NB + b];
        bool mv;
        if (kind == 0)      mv = ((const unsigned char*)maskraw)[b*NTOK + n] != 0;
        else if (kind == 1) mv = ((const float*)maskraw)[b*NTOK + n] != 0.0f;
        else                mv = ((const int*)maskraw)[b*NTOK + n] != 0;
        unsigned char c = 0;
        if (!mv) c = (s >= 0.5f) ? 1 : 2;
        cat[n] = c; keys[n] = __float_as_uint(s);
        if (c == 1) lc1++; else if (c == 2) lc2++;
    }
    atomicAdd(&sC1, lc1); atomicAdd(&sC2, lc2);
    __syncthreads();
    int kcnt = min(sC1, sC2);

    if (kcnt == 0) {
        for (int n = tid; n < NTOK; n += 512) g_cat[n*NB + b] = 0;
        if (tid == 0) g_minCnt[b] = 0;
        return;
    }

    unsigned int thr[2]; int kkEq[2];
    for (int c = 1; c <= 2; c++) {
        unsigned int pfx = 0; int kk = kcnt;
        for (int p = 24; p >= 0; p -= 8) {
            if (tid < 256) hist[tid] = 0;
            __syncthreads();
            for (int n = tid; n < NTOK; n += 512) {
                if (cat[n] == (unsigned char)c) {
                    unsigned int u = keys[n];
                    if ((((unsigned long long)(u ^ pfx)) >> (p + 8)) == 0ull)
                        atomicAdd(&hist[(u >> p) & 255], 1);
                }
            }
            __syncthreads();
            // parallel suffix-sum digit selection:
            // sfxArr[t] = sum_{d >= 255-t} hist[d] (t ascending = d descending)
            {
                int v = (tid < 256) ? hist[255 - tid] : 0;
                int inc = v;
                #pragma unroll
                for (int off = 1; off < 32; off <<= 1) {
                    int t2 = __shfl_up_sync(0xffffffffu, inc, off);
                    if (lane >= off) inc += t2;
                }
                if (tid < 256 && lane == 31) wT[tid >> 5] = inc;
                __syncthreads();
                if (tid == 0) { int run = 0; for (int i = 0; i < 8; i++) { int t2 = wT[i]; wT[i] = run; run += t2; } }
                __syncthreads();
                if (tid < 256) sfxArr[tid] = inc + wT[tid >> 5];
                __syncthreads();
                if (tid < 256) {
                    int mine = sfxArr[tid];
                    int prev = (tid == 0) ? 0 : sfxArr[tid - 1];   // = s[d+1]
                    if (mine >= kk && prev < kk) {
                        int d = 255 - tid;
                        sPfx = pfx | ((unsigned)d << p);
                        sKK  = kk - prev;
                    }
                }
            }
            __syncthreads();
            pfx = sPfx; kk = sKK;
            __syncthreads();
        }
        thr[c-1] = pfx; kkEq[c-1] = kk;
    }

    for (int n = tid; n < NTOK; n += 512) {
        int f = 0;
        if (cat[n] == 1 && keys[n] == thr[0]) f = 1;
        if (cat[n] == 2 && keys[n] == thr[1]) f |= 1 << 16;
        sIdx[n] = f;
    }
    __syncthreads();
    scan4096_512(sIdx);

    for (int n = tid; n < NTOK; n += 512) {
        unsigned char c = cat[n], c2 = 0;
        if (c == 1) {
            if (keys[n] > thr[0] || (keys[n] == thr[0] && (sIdx[n] & 0xffff) < kkEq[0])) c2 = 1;
        } else if (c == 2) {
            if (keys[n] > thr[1] || (keys[n] == thr[1] && (sIdx[n] >> 16) < kkEq[1])) c2 = 2;
        }
        cat[n] = c2;
    }
    __syncthreads();

    for (int n = tid; n < NTOK; n += 512)
        keys[n] = (unsigned)((cat[n] == 1 ? 1 : 0) | ((cat[n] == 2 ? 1 : 0) << 16));
    __syncthreads();
    scan4096_512((int*)keys);

    for (int n = tid; n < NTOK; n += 512)
        if (cat[n] == 1) sIdx[(int)(keys[n] & 0xffff)] = n;
    __syncthreads();

    for (int n = tid; n < NTOK; n += 512) {
        g_cat[n*NB + b] = cat[n];
        if (cat[n] == 1) {
            int r = (int)(keys[n] & 0xffff);
            g_splitWork[b*NTOK + r] = n | (n << 16);
        } else if (cat[n] == 2) {
            int r = (int)(keys[n] >> 16);
            g_pairWork[b*NTOK + r] = n | (sIdx[r] << 16);
        }
    }
    if (tid == 0) g_minCnt[b] = kcnt;
}

// ---------------- K3: selective z GEMM, gathered A, scattered epilogue ----------------
__global__ __launch_bounds__(128) void kZM(
    const float* __restrict__ x, const float* __restrict__ ws,
    const float* __restrict__ bs, float* __restrict__ out)
{
    int b = blockIdx.y, ct = blockIdx.z, half = ct >> 1;
    int rows = g_minCnt[b];
    int r0 = blockIdx.x * 64;
    if (r0 >= rows) return;

    extern __shared__ float smf[];
    uint32_t sb = smem_u32(smf);
    float* biasl = smf + 2*BUFBYTES/4;     // 128
    int*   srcs  = (int*)(biasl + 128);    // 64
    int*   dsts  = srcs + 64;              // 64
    int tid = threadIdx.x, wid = tid >> 5, lane = tid & 31;
    int warpM = wid & 1, warpN = wid >> 1;
    int nr = min(64, rows - r0);

    biasl[tid] = bs[ct * 128 + tid];
    if (tid < 64) {
        if (tid < nr) {
            srcs[tid] = g_splitWork[b*NTOK + r0 + tid] & 0xffff;
            dsts[tid] = (half ? g_pairWork : g_splitWork)[b*NTOK + r0 + tid] & 0xffff;
        } else { srcs[tid] = 0; dsts[tid] = -1; }
    }
    __syncthreads();

    float acc[2][8][4];
    #pragma unroll
    for (int mt = 0; mt < 2; mt++)
        #pragma unroll
        for (int nt = 0; nt < 8; nt++)
            #pragma unroll
            for (int q = 0; q < 4; q++) acc[mt][nt][q] = 0.f;

    auto issue = [&](int c, int buf){
        int k0 = c * 32;
        uint32_t ab = sb + buf * BUFBYTES;
        #pragma unroll
        for (int t = 0; t < 4; t++) {
            int s = tid + t*128, r = s >> 3, seg = s & 7;
            CP16(ab + r*(ASTR*4) + seg*16,
                 x + (size_t)(srcs[r]*NB + b)*NC + k0 + seg*4);
        }
        uint32_t bb = sb + buf * BUFBYTES + ABYTES;
        #pragma unroll
        for (int t = 0; t < 8; t++) {
            int s = tid + t*128, k = s >> 5, seg = s & 31;
            CP16(bb + k*(BSTR*4) + seg*16,
                 ws + (size_t)(k0 + k)*512 + ct*128 + seg*4);
        }
    };

    issue(0, 0); CPCOMMIT();
    for (int c = 0; c < 8; c++) {
        if (c < 7) { issue(c+1, (c+1)&1); CPCOMMIT(); CPWAIT1(); }
        else CPWAIT0();
        __syncthreads();
        const float* As = smf + (c&1)*(BUFBYTES/4);
        const float* Bs = As + ABYTES/4;
        computeChunk(As, Bs, warpM, warpN, lane, acc);
        __syncthreads();
    }

    int outColBase = (ct & 1) * 128;
    #pragma unroll
    for (int mt = 0; mt < 2; mt++) {
        int rA = warpM*32 + mt*16 + (lane >> 2);
        int d0 = dsts[rA], d1 = dsts[rA + 8];
        #pragma unroll
        for (int nt = 0; nt < 8; nt++) {
            int c0 = warpN*64 + nt*8 + (lane & 3)*2;
            float bb0 = biasl[c0], bb1 = biasl[c0+1];
            if (d0 >= 0) {
                float2 o; o.x = fmaxf(acc[mt][nt][0] + bb0, 0.f);
                          o.y = fmaxf(acc[mt][nt][1] + bb1, 0.f);
                *(float2*)(out + (size_t)(d0*NB + b)*NC + outColBase + c0) = o;
            }
            if (d1 >= 0) {
                float2 o; o.x = fmaxf(acc[mt][nt][2] + bb0, 0.f);
                          o.y = fmaxf(acc[mt][nt][3] + bb1, 0.f);
                *(float2*)(out + (size_t)(d1*NB + b)*NC + outColBase + c0) = o;
            }
        }
    }
}

// ---------------- K4: passthrough copy ----------------
__global__ void kCopy(const float* __restrict__ x, float* __restrict__ out)
{
    int idx = blockIdx.x * 256 + threadIdx.x;
    int t = idx >> 6;
    if (g_cat[t] == 0)
        ((float4*)out)[idx] = ((const float4*)x)[idx];
}

// ---------------- launch ----------------
extern "C" void kernel_launch(void* const* d_in, const int* in_sizes, int n_in,
                              void* d_out, int out_size)
{
    const float* x  = (const float*)d_in[0];
    const void*  mk = d_in[1];
    const float* w1 = (const float*)d_in[2];
    const float* b1 = (const float*)d_in[3];
    const float* w2 = (const float*)d_in[4];
    const float* b2 = (const float*)d_in[5];
    const float* ws = (const float*)d_in[6];
    const float* bs = (const float*)d_in[7];
    float* out = (float*)d_out;

    cudaFuncSetAttribute(kLogitM, cudaFuncAttributeMaxDynamicSharedMemorySize, SMEMREQ);
    cudaFuncSetAttribute(kZM,     cudaFuncAttributeMaxDynamicSharedMemorySize, SMEMREQ);

    kProbe<<<1, 256>>>((const unsigned char*)mk);
    kLogitM<<<TOTAL/64, 128, SMEMREQ>>>(x, w1, b1, w2, b2);
    kSelect<<<NB, 512>>>(mk);
    dim3 gz(32, NB, 4);
    kZM<<<gz, 128, SMEMREQ>>>(x, ws, bs, out);
    kCopy<<<TOTAL/4, 256>>>(x, out);
}

// round 10
// speedup vs baseline: 2.5642x; 1.2233x over previous
#include <cuda_runtime.h>
#include <math.h>
#include <stdint.h>

#define NTOK 4096
#define NB   16
#define NC   256
#define TOTAL (NTOK*NB)
#define ASTR 36
#define BSTR 132
#define ABYTES (64*ASTR*4)
#define BBYTES (32*BSTR*4)
#define BUFBYTES (ABYTES+BBYTES)
#define SMEMREQ (2*BUFBYTES + 2048)

// ---------------- device scratch ----------------
__device__ float         g_sig[TOTAL];
__device__ unsigned char g_cat[TOTAL];
__device__ int           g_splitWork[TOTAL];
__device__ int           g_pairWork[TOTAL];
__device__ int           g_minCnt[NB];

// ---------------- helpers ----------------
__device__ __forceinline__ uint32_t smem_u32(const void* p){
    uint32_t a;
    asm("{ .reg .u64 t; cvta.to.shared.u64 t, %1; cvt.u32.u64 %0, t; }" : "=r"(a) : "l"(p));
    return a;
}
__device__ __forceinline__ void tf32split(float v, uint32_t& hi, uint32_t& lo){
    asm("cvt.rna.tf32.f32 %0, %1;" : "=r"(hi) : "f"(v));
    float l = v - __uint_as_float(hi);
    asm("cvt.rna.tf32.f32 %0, %1;" : "=r"(lo) : "f"(l));
}
__device__ __forceinline__ void mma8(float* d, const uint32_t* a, const uint32_t* b){
    asm volatile("mma.sync.aligned.m16n8k8.row.col.f32.tf32.tf32.f32 "
        "{%0,%1,%2,%3}, {%4,%5,%6,%7}, {%8,%9}, {%0,%1,%2,%3};"
        : "+f"(d[0]),"+f"(d[1]),"+f"(d[2]),"+f"(d[3])
        : "r"(a[0]),"r"(a[1]),"r"(a[2]),"r"(a[3]), "r"(b[0]),"r"(b[1]));
}
__device__ __forceinline__ void mma16(float* d, const uint32_t* a, const uint32_t* b){
    asm volatile("mma.sync.aligned.m16n8k16.row.col.f32.bf16.bf16.f32 "
        "{%0,%1,%2,%3}, {%4,%5,%6,%7}, {%8,%9}, {%0,%1,%2,%3};"
        : "+f"(d[0]),"+f"(d[1]),"+f"(d[2]),"+f"(d[3])
        : "r"(a[0]),"r"(a[1]),"r"(a[2]),"r"(a[3]), "r"(b[0]),"r"(b[1]));
}
// pack (v0 lower, v1 upper) hi-bf16 pair + lo-bf16 pair
__device__ __forceinline__ void bfsplit2(float v0, float v1, uint32_t& ph, uint32_t& pl){
    asm("cvt.rn.bf16x2.f32 %0, %1, %2;" : "=r"(ph) : "f"(v1), "f"(v0));
    float h0 = __uint_as_float((ph & 0xffffu) << 16);
    float h1 = __uint_as_float(ph & 0xffff0000u);
    float l0 = v0 - h0, l1 = v1 - h1;
    asm("cvt.rn.bf16x2.f32 %0, %1, %2;" : "=r"(pl) : "f"(l1), "f"(l0));
}
#define CP16(dst, src) asm volatile("cp.async.cg.shared.global [%0], [%1], 16;" :: "r"(dst), "l"(src))
#define CPCOMMIT()     asm volatile("cp.async.commit_group;" ::: "memory")
#define CPWAIT1()      asm volatile("cp.async.wait_group 1;" ::: "memory")
#define CPWAIT0()      asm volatile("cp.async.wait_group 0;" ::: "memory")

// ================= tf32 compute core (kLogitM, precision-critical) =================
__device__ __forceinline__ void computeChunk(
    const float* As, const float* Bs, int warpM, int warpN, int lane,
    float acc[2][8][4])
{
    #pragma unroll
    for (int ks = 0; ks < 4; ks++) {
        int kk = ks * 8;
        uint32_t aH[2][4], aL[2][4];
        #pragma unroll
        for (int mt = 0; mt < 2; mt++) {
            int rb = warpM*32 + mt*16 + (lane >> 2);
            int cc = kk + (lane & 3);
            tf32split(As[rb*ASTR + cc],        aH[mt][0], aL[mt][0]);
            tf32split(As[(rb+8)*ASTR + cc],    aH[mt][1], aL[mt][1]);
            tf32split(As[rb*ASTR + cc + 4],    aH[mt][2], aL[mt][2]);
            tf32split(As[(rb+8)*ASTR + cc + 4],aH[mt][3], aL[mt][3]);
        }
        #pragma unroll
        for (int nt = 0; nt < 8; nt++) {
            int nb = warpN*64 + nt*8 + (lane >> 2);
            int kr = kk + (lane & 3);
            uint32_t bH[2], bL[2];
            tf32split(Bs[kr*BSTR + nb],       bH[0], bL[0]);
            tf32split(Bs[(kr+4)*BSTR + nb],   bH[1], bL[1]);
            #pragma unroll
            for (int mt = 0; mt < 2; mt++) {
                mma8(acc[mt][nt], aH[mt], bH);
                mma8(acc[mt][nt], aH[mt], bL);
                mma8(acc[mt][nt], aL[mt], bH);
            }
        }
    }
}

// ================= bf16x3 compute core (kZM, output tolerance 1e-3) =================
__device__ __forceinline__ void computeChunkBF(
    const float* As, const float* Bs, int warpM, int warpN, int lane,
    float acc[2][8][4])
{
    #pragma unroll
    for (int ks = 0; ks < 2; ks++) {
        int kk = ks * 16;
        uint32_t aH[2][4], aL[2][4];
        #pragma unroll
        for (int mt = 0; mt < 2; mt++) {
            int rb = warpM*32 + mt*16 + (lane >> 2);
            int c0 = kk + (lane & 3)*2;
            bfsplit2(As[rb*ASTR + c0],       As[rb*ASTR + c0 + 1],     aH[mt][0], aL[mt][0]);
            bfsplit2(As[(rb+8)*ASTR + c0],   As[(rb+8)*ASTR + c0 + 1], aH[mt][1], aL[mt][1]);
            bfsplit2(As[rb*ASTR + c0 + 8],   As[rb*ASTR + c0 + 9],     aH[mt][2], aL[mt][2]);
            bfsplit2(As[(rb+8)*ASTR + c0+8], As[(rb+8)*ASTR + c0 + 9], aH[mt][3], aL[mt][3]);
        }
        #pragma unroll
        for (int nt = 0; nt < 8; nt++) {
            int nb = warpN*64 + nt*8 + (lane >> 2);
            int kr = kk + (lane & 3)*2;
            uint32_t bH[2], bL[2];
            bfsplit2(Bs[kr*BSTR + nb],     Bs[(kr+1)*BSTR + nb], bH[0], bL[0]);
            bfsplit2(Bs[(kr+8)*BSTR + nb], Bs[(kr+9)*BSTR + nb], bH[1], bL[1]);
            #pragma unroll
            for (int mt = 0; mt < 2; mt++) {
                mma16(acc[mt][nt], aH[mt], bH);
                mma16(acc[mt][nt], aH[mt], bL);
                mma16(acc[mt][nt], aL[mt], bH);
            }
        }
    }
}

// ---------------- K1: gate GEMM (tf32x3), fused relu/w2/sigmoid ----------------
__global__ __launch_bounds__(128) void kLogitM(
    const float* __restrict__ x,  const float* __restrict__ w1,
    const float* __restrict__ b1, const float* __restrict__ w2,
    const float* __restrict__ b2)
{
    extern __shared__ float smf[];
    uint32_t sb = smem_u32(smf);
    float* b1s = smf + 2*BUFBYTES/4;
    float* w2s = b1s + 128;
    float* sLog = w2s + 128;
    int tid = threadIdx.x, wid = tid >> 5, lane = tid & 31;
    int warpM = wid & 1, warpN = wid >> 1;
    int tileBase = blockIdx.x * 64;

    b1s[tid] = b1[tid]; w2s[tid] = w2[tid];
    if (tid < 64) sLog[tid] = 0.f;

    float acc[2][8][4];
    #pragma unroll
    for (int mt = 0; mt < 2; mt++)
        #pragma unroll
        for (int nt = 0; nt < 8; nt++)
            #pragma unroll
            for (int q = 0; q < 4; q++) acc[mt][nt][q] = 0.f;

    auto issue = [&](int c, int buf){
        int k0 = c * 32;
        uint32_t ab = sb + buf * BUFBYTES;
        #pragma unroll
        for (int t = 0; t < 4; t++) {
            int s = tid + t*128, r = s >> 3, seg = s & 7;
            CP16(ab + r*(ASTR*4) + seg*16,
                 x + (size_t)(tileBase + r)*NC + k0 + seg*4);
        }
        uint32_t bb = sb + buf * BUFBYTES + ABYTES;
        #pragma unroll
        for (int t = 0; t < 8; t++) {
            int s = tid + t*128, k = s >> 5, seg = s & 31;
            CP16(bb + k*(BSTR*4) + seg*16,
                 w1 + (size_t)(k0 + k)*128 + seg*4);
        }
    };

    issue(0, 0); CPCOMMIT();
    for (int c = 0; c < 8; c++) {
        if (c < 7) { issue(c+1, (c+1)&1); CPCOMMIT(); CPWAIT1(); }
        else CPWAIT0();
        __syncthreads();
        const float* As = smf + (c&1)*(BUFBYTES/4);
        const float* Bs = As + ABYTES/4;
        computeChunk(As, Bs, warpM, warpN, lane, acc);
        __syncthreads();
    }

    #pragma unroll
    for (int mt = 0; mt < 2; mt++) {
        float p0 = 0.f, p1 = 0.f;
        #pragma unroll
        for (int nt = 0; nt < 8; nt++) {
            int c0 = warpN*64 + nt*8 + (lane & 3)*2, c1 = c0 + 1;
            p0 += fmaxf(acc[mt][nt][0] + b1s[c0], 0.f) * w2s[c0]
                + fmaxf(acc[mt][nt][1] + b1s[c1], 0.f) * w2s[c1];
            p1 += fmaxf(acc[mt][nt][2] + b1s[c0], 0.f) * w2s[c0]
                + fmaxf(acc[mt][nt][3] + b1s[c1], 0.f) * w2s[c1];
        }
        p0 += __shfl_xor_sync(0xffffffffu, p0, 1); p0 += __shfl_xor_sync(0xffffffffu, p0, 2);
        p1 += __shfl_xor_sync(0xffffffffu, p1, 1); p1 += __shfl_xor_sync(0xffffffffu, p1, 2);
        if ((lane & 3) == 0) {
            int r = warpM*32 + mt*16 + (lane >> 2);
            atomicAdd(sLog + r, p0);
            atomicAdd(sLog + r + 8, p1);
        }
    }
    __syncthreads();
    if (tid < 64) {
        float logit = sLog[tid] + b2[0];
        g_sig[tileBase + tid] = 1.0f / (1.0f + expf(-logit));
    }
}

// ---------------- block exclusive scan over 4096 ints, 512 threads ----------------
__device__ __forceinline__ void scan4096_512(int* A)
{
    __shared__ int wS[16];
    int tid = threadIdx.x;
    int base = tid * 8;
    int loc[8]; int sum = 0;
    #pragma unroll
    for (int i = 0; i < 8; i++) { int v = A[base + i]; loc[i] = sum; sum += v; }
    int lane = tid & 31, w = tid >> 5;
    int inc = sum;
    #pragma unroll
    for (int off = 1; off < 32; off <<= 1) {
        int t = __shfl_up_sync(0xffffffffu, inc, off);
        if (lane >= off) inc += t;
    }
    if (lane == 31) wS[w] = inc;
    __syncthreads();
    if (tid == 0) { int run = 0; for (int i = 0; i < 16; i++) { int t = wS[i]; wS[i] = run; run += t; } }
    __syncthreads();
    int off = wS[w] + (inc - sum);
    #pragma unroll
    for (int i = 0; i < 8; i++) A[base + i] = off + loc[i];
    __syncthreads();
}

// ---------------- K2: per-batch selection (probe fused, dual-class radix) ----------------
__global__ __launch_bounds__(512,1) void kSelect(const void* __restrict__ maskraw)
{
    __shared__ unsigned int keys[NTOK];
    __shared__ unsigned char cat[NTOK];
    __shared__ int sIdx[NTOK];
    __shared__ int hist2[512];          // [0:256) class1, [256:512) class2
    __shared__ int wT[16];
    __shared__ unsigned int sPfxA[2];
    __shared__ int sKKA[2];
    __shared__ int sC1, sC2, sPA, sP3;

    int b = blockIdx.x, tid = threadIdx.x;
    int lane = tid & 31;
    if (tid == 0) { sC1 = 0; sC2 = 0; sPA = 0; sP3 = 0; }
    __syncthreads();

    // inline mask-dtype probe over first 4KB (L2-cached, all blocks redundant)
    {
        const unsigned char* m = (const unsigned char*)maskraw;
        int la = 0, l3 = 0;
        for (int i = tid; i < 4096; i += 512) {
            unsigned char v = m[i];
            if ((i & 3) == 1 && v) la++;
            if ((i & 3) == 3 && v == 0x3F) l3++;
        }
        atomicAdd(&sPA, la); atomicAdd(&sP3, l3);
    }
    __syncthreads();
    int kind = (sPA > 0) ? 0 : ((sP3 > 0) ? 1 : 2);

    int lc1 = 0, lc2 = 0;
    for (int n = tid; n < NTOK; n += 512) {
        float s = g_sig[n*NB + b];
        bool mv;
        if (kind == 0)      mv = ((const unsigned char*)maskraw)[b*NTOK + n] != 0;
        else if (kind == 1) mv = ((const float*)maskraw)[b*NTOK + n] != 0.0f;
        else                mv = ((const int*)maskraw)[b*NTOK + n] != 0;
        unsigned char c = 0;
        if (!mv) c = (s >= 0.5f) ? 1 : 2;
        cat[n] = c; keys[n] = __float_as_uint(s);
        if (c == 1) lc1++; else if (c == 2) lc2++;
    }
    atomicAdd(&sC1, lc1); atomicAdd(&sC2, lc2);
    __syncthreads();
    int kcnt = min(sC1, sC2);

    if (kcnt == 0) {
        for (int n = tid; n < NTOK; n += 512) g_cat[n*NB + b] = 0;
        if (tid == 0) g_minCnt[b] = 0;
        return;
    }

    // dual-class MSB radix select: both classes per pass
    unsigned int pfx0 = 0, pfx1 = 0; int kk0 = kcnt, kk1 = kcnt;
    for (int p = 24; p >= 0; p -= 8) {
        hist2[tid] = 0;
        __syncthreads();
        for (int n = tid; n < NTOK; n += 512) {
            unsigned char c = cat[n];
            if (c) {
                unsigned int u = keys[n];
                unsigned int pf = (c == 1) ? pfx0 : pfx1;
                if ((((unsigned long long)(u ^ pf)) >> (p + 8)) == 0ull)
                    atomicAdd(&hist2[((int)(c-1) << 8) + ((u >> p) & 255)], 1);
            }
        }
        __syncthreads();
        // parallel suffix-sum per half: tid<256 class1, tid>=256 class2
        {
            int ci = tid >> 8, t = tid & 255;
            int kkc = ci ? kk1 : kk0;
            int v = hist2[(ci << 8) + (255 - t)];
            int inc = v;
            #pragma unroll
            for (int off = 1; off < 32; off <<= 1) {
                int t2 = __shfl_up_sync(0xffffffffu, inc, off);
                if (lane >= off) inc += t2;
            }
            if (lane == 31) wT[tid >> 5] = inc;
            __syncthreads();
            if ((tid & 255) == 0) {
                int base = ci * 8; int run = 0;
                for (int i = 0; i < 8; i++) { int t2 = wT[base + i]; wT[base + i] = run; run += t2; }
            }
            __syncthreads();
            int sfx = inc + wT[tid >> 5];
            // prev (= suffix starting one digit higher) via shfl / shared read
            int prev;
            if (lane == 0) prev = (t == 0) ? 0 : (hist2[(ci << 8) + (256 - t)] /*unused*/ , 0) ;
            // compute prev robustly: prev = sfx - v is the suffix EXCLUDING this digit? No:
            // sfx includes digits d..255 (d = 255-t). prev = suffix for d+1..255 = sfx - v.
            prev = sfx - v;
            if (sfx >= kkc && prev < kkc) {
                int d = 255 - t;
                unsigned int pf = ci ? pfx1 : pfx0;
                sPfxA[ci] = pf | ((unsigned)d << p);
                sKKA[ci]  = kkc - prev;
            }
        }
        __syncthreads();
        pfx0 = sPfxA[0]; kk0 = sKKA[0];
        pfx1 = sPfxA[1]; kk1 = sKKA[1];
        __syncthreads();
    }
    unsigned int thr[2] = {pfx0, pfx1};
    int kkEq[2] = {kk0, kk1};

    for (int n = tid; n < NTOK; n += 512) {
        int f = 0;
        if (cat[n] == 1 && keys[n] == thr[0]) f = 1;
        if (cat[n] == 2 && keys[n] == thr[1]) f |= 1 << 16;
        sIdx[n] = f;
    }
    __syncthreads();
    scan4096_512(sIdx);

    for (int n = tid; n < NTOK; n += 512) {
        unsigned char c = cat[n], c2 = 0;
        if (c == 1) {
            if (keys[n] > thr[0] || (keys[n] == thr[0] && (sIdx[n] & 0xffff) < kkEq[0])) c2 = 1;
        } else if (c == 2) {
            if (keys[n] > thr[1] || (keys[n] == thr[1] && (sIdx[n] >> 16) < kkEq[1])) c2 = 2;
        }
        cat[n] = c2;
    }
    __syncthreads();

    for (int n = tid; n < NTOK; n += 512)
        keys[n] = (unsigned)((cat[n] == 1 ? 1 : 0) | ((cat[n] == 2 ? 1 : 0) << 16));
    __syncthreads();
    scan4096_512((int*)keys);

    for (int n = tid; n < NTOK; n += 512)
        if (cat[n] == 1) sIdx[(int)(keys[n] & 0xffff)] = n;
    __syncthreads();

    for (int n = tid; n < NTOK; n += 512) {
        g_cat[n*NB + b] = cat[n];
        if (cat[n] == 1) {
            int r = (int)(keys[n] & 0xffff);
            g_splitWork[b*NTOK + r] = n | (n << 16);
        } else if (cat[n] == 2) {
            int r = (int)(keys[n] >> 16);
            g_pairWork[b*NTOK + r] = n | (sIdx[r] << 16);
        }
    }
    if (tid == 0) g_minCnt[b] = kcnt;
}

// ---------------- K3: selective z GEMM (bf16x3), gathered A, scattered epilogue ----------------
__global__ __launch_bounds__(128) void kZM(
    const float* __restrict__ x, const float* __restrict__ ws,
    const float* __restrict__ bs, float* __restrict__ out)
{
    int b = blockIdx.y, ct = blockIdx.z, half = ct >> 1;
    int rows = g_minCnt[b];
    int r0 = blockIdx.x * 64;
    if (r0 >= rows) return;

    extern __shared__ float smf[];
    uint32_t sb = smem_u32(smf);
    float* biasl = smf + 2*BUFBYTES/4;
    int*   srcs  = (int*)(biasl + 128);
    int*   dsts  = srcs + 64;
    int tid = threadIdx.x, wid = tid >> 5, lane = tid & 31;
    int warpM = wid & 1, warpN = wid >> 1;
    int nr = min(64, rows - r0);

    biasl[tid] = bs[ct * 128 + tid];
    if (tid < 64) {
        if (tid < nr) {
            srcs[tid] = g_splitWork[b*NTOK + r0 + tid] & 0xffff;
            dsts[tid] = (half ? g_pairWork : g_splitWork)[b*NTOK + r0 + tid] & 0xffff;
        } else { srcs[tid] = 0; dsts[tid] = -1; }
    }
    __syncthreads();

    float acc[2][8][4];
    #pragma unroll
    for (int mt = 0; mt < 2; mt++)
        #pragma unroll
        for (int nt = 0; nt < 8; nt++)
            #pragma unroll
            for (int q = 0; q < 4; q++) acc[mt][nt][q] = 0.f;

    auto issue = [&](int c, int buf){
        int k0 = c * 32;
        uint32_t ab = sb + buf * BUFBYTES;
        #pragma unroll
        for (int t = 0; t < 4; t++) {
            int s = tid + t*128, r = s >> 3, seg = s & 7;
            CP16(ab + r*(ASTR*4) + seg*16,
                 x + (size_t)(srcs[r]*NB + b)*NC + k0 + seg*4);
        }
        uint32_t bb = sb + buf * BUFBYTES + ABYTES;
        #pragma unroll
        for (int t = 0; t < 8; t++) {
            int s = tid + t*128, k = s >> 5, seg = s & 31;
            CP16(bb + k*(BSTR*4) + seg*16,
                 ws + (size_t)(k0 + k)*512 + ct*128 + seg*4);
        }
    };

    issue(0, 0); CPCOMMIT();
    for (int c = 0; c < 8; c++) {
        if (c < 7) { issue(c+1, (c+1)&1); CPCOMMIT(); CPWAIT1(); }
        else CPWAIT0();
        __syncthreads();
        const float* As = smf + (c&1)*(BUFBYTES/4);
        const float* Bs = As + ABYTES/4;
        computeChunkBF(As, Bs, warpM, warpN, lane, acc);
        __syncthreads();
    }

    int outColBase = (ct & 1) * 128;
    #pragma unroll
    for (int mt = 0; mt < 2; mt++) {
        int rA = warpM*32 + mt*16 + (lane >> 2);
        int d0 = dsts[rA], d1 = dsts[rA + 8];
        #pragma unroll
        for (int nt = 0; nt < 8; nt++) {
            int c0 = warpN*64 + nt*8 + (lane & 3)*2;
            float bb0 = biasl[c0], bb1 = biasl[c0+1];
            if (d0 >= 0) {
                float2 o; o.x = fmaxf(acc[mt][nt][0] + bb0, 0.f);
                          o.y = fmaxf(acc[mt][nt][1] + bb1, 0.f);
                *(float2*)(out + (size_t)(d0*NB + b)*NC + outColBase + c0) = o;
            }
            if (d1 >= 0) {
                float2 o; o.x = fmaxf(acc[mt][nt][2] + bb0, 0.f);
                          o.y = fmaxf(acc[mt][nt][3] + bb1, 0.f);
                *(float2*)(out + (size_t)(d1*NB + b)*NC + outColBase + c0) = o;
            }
        }
    }
}

// ---------------- K4: passthrough copy ----------------
__global__ void kCopy(const float* __restrict__ x, float* __restrict__ out)
{
    int idx = blockIdx.x * 256 + threadIdx.x;
    int t = idx >> 6;
    if (g_cat[t] == 0)
        ((float4*)out)[idx] = ((const float4*)x)[idx];
}

// ---------------- launch ----------------
extern "C" void kernel_launch(void* const* d_in, const int* in_sizes, int n_in,
                              void* d_out, int out_size)
{
    const float* x  = (const float*)d_in[0];
    const void*  mk = d_in[1];
    const float* w1 = (const float*)d_in[2];
    const float* b1 = (const float*)d_in[3];
    const float* w2 = (const float*)d_in[4];
    const float* b2 = (const float*)d_in[5];
    const float* ws = (const float*)d_in[6];
    const float* bs = (const float*)d_in[7];
    float* out = (float*)d_out;

    cudaFuncSetAttribute(kLogitM, cudaFuncAttributeMaxDynamicSharedMemorySize, SMEMREQ);
    cudaFuncSetAttribute(kZM,     cudaFuncAttributeMaxDynamicSharedMemorySize, SMEMREQ);

    kLogitM<<<TOTAL/64, 128, SMEMREQ>>>(x, w1, b1, w2, b2);
    kSelect<<<NB, 512>>>(mk);
    dim3 gz(32, NB, 4);
    kZM<<<gz, 128, SMEMREQ>>>(x, ws, bs, out);
    kCopy<<<TOTAL/4, 256>>>(x, out);
}